// round 1
// baseline (speedup 1.0000x reference)
#include <cuda_runtime.h>
#include <math.h>

// ---------------------------------------------------------------------------
// MoE (dense-reference) computed sparsely: route first, run only top-2 experts.
// B=8, S=4096 -> T=32768 tokens. D=256, H=256, E=6, TOP_K=2, ROUTER_H=128.
// Output is mathematically identical to the dense reference.
// ---------------------------------------------------------------------------

#define E_NUM   6
#define D_DIM   256
#define H_DIM   256
#define RH_DIM  128
#define TOPK    2
#define MAX_T   32768
#define TM      64      // tokens per tile
#define LDT     68      // padded leading dim for transposed activation tiles

// Scratch: per-expert token lists (built by router each launch). No allocation
// inside kernel_launch -> __device__ globals.
__device__ int   g_counts[E_NUM];
__device__ int   g_tok[E_NUM * MAX_T];
__device__ float g_wt [E_NUM * MAX_T];

// ---------------------------------------------------------------------------
// Zero output + routing counters (graph replays must re-zero every time).
// ---------------------------------------------------------------------------
__global__ void zero_kernel(float4* __restrict__ out4, int n4)
{
    if (blockIdx.x == 0 && threadIdx.x < E_NUM) g_counts[threadIdx.x] = 0;
    int i = blockIdx.x * blockDim.x + threadIdx.x;
    int stride = gridDim.x * blockDim.x;
    float4 z = make_float4(0.f, 0.f, 0.f, 0.f);
    for (int k = i; k < n4; k += stride) out4[k] = z;
}

// ---------------------------------------------------------------------------
// Router: per 64-token tile:
//   RH = relu(X @ W1 + b1)      [64 x 128]
//   logits = RH @ W2 + b2       [64 x 6]
//   p = softmax(logits); top-2; w = softmax(top-2 p values)
//   append (token, weight) to per-expert lists (block-aggregated atomics)
// ---------------------------------------------------------------------------
__global__ void __launch_bounds__(256)
router_kernel(const float* __restrict__ feat,
              const float* __restrict__ rw1, const float* __restrict__ rb1,
              const float* __restrict__ rw2, const float* __restrict__ rb2,
              int T)
{
    extern __shared__ float sm[];
    float* sXT = sm;                         // [256][LDT]  X^T
    float* sRT = sXT + D_DIM * LDT;          // [128][LDT]  RH^T
    float* sW  = sRT + RH_DIM * LDT;         // [32][128]   W1 k-stage
    float* sW2 = sW + 32 * RH_DIM;           // [128*6]     W2 (whole)

    __shared__ int s_cnt[E_NUM];
    __shared__ int s_base[E_NUM];

    int tid = threadIdx.x;
    int tx = tid & 31, ty = tid >> 5;
    int t0 = blockIdx.x * TM;
    int rows = min(TM, T - t0);

    if (tid < E_NUM) s_cnt[tid] = 0;
    for (int i = tid; i < RH_DIM * E_NUM; i += 256) sW2[i] = rw2[i];

    // gather X^T (clamp OOB rows to row 0 of the tile; writes guarded later)
    for (int idx = tid; idx < TM * (D_DIM / 4); idx += 256) {
        int m  = idx >> 6;          // token row within tile (D_DIM/4==64)
        int c4 = idx & 63;
        int trow = t0 + ((m < rows) ? m : 0);
        float4 v = reinterpret_cast<const float4*>(feat + (size_t)trow * D_DIM)[c4];
        int k = c4 * 4;
        sXT[(k + 0) * LDT + m] = v.x;
        sXT[(k + 1) * LDT + m] = v.y;
        sXT[(k + 2) * LDT + m] = v.z;
        sXT[(k + 3) * LDT + m] = v.w;
    }

    // GEMM1: 64x128, K=256. Thread tile: m = ty*8+i (8), n = tx+32*j (4).
    float c[8][4];
    #pragma unroll
    for (int j = 0; j < 4; j++) {
        float bv = rb1[tx + 32 * j];
        #pragma unroll
        for (int i = 0; i < 8; i++) c[i][j] = bv;
    }
    for (int k0 = 0; k0 < D_DIM; k0 += 32) {
        __syncthreads();
        #pragma unroll
        for (int i = 0; i < 4; i++) {
            int idx = tid + i * 256;                 // 1024 float4 total
            int kk = idx >> 5, c4 = idx & 31;
            reinterpret_cast<float4*>(sW + kk * RH_DIM)[c4] =
                reinterpret_cast<const float4*>(rw1 + (size_t)(k0 + kk) * RH_DIM)[c4];
        }
        __syncthreads();
        #pragma unroll 4
        for (int kk = 0; kk < 32; kk++) {
            const float* arow = sXT + (k0 + kk) * LDT + ty * 8;
            float4 a0 = *reinterpret_cast<const float4*>(arow);
            float4 a1 = *reinterpret_cast<const float4*>(arow + 4);
            float a[8] = {a0.x, a0.y, a0.z, a0.w, a1.x, a1.y, a1.z, a1.w};
            float bb[4];
            #pragma unroll
            for (int j = 0; j < 4; j++) bb[j] = sW[kk * RH_DIM + tx + 32 * j];
            #pragma unroll
            for (int i = 0; i < 8; i++)
                #pragma unroll
                for (int j = 0; j < 4; j++) c[i][j] += a[i] * bb[j];
        }
    }
    // relu + store RH^T
    #pragma unroll
    for (int j = 0; j < 4; j++) {
        int n = tx + 32 * j;
        float4 v0 = make_float4(fmaxf(c[0][j], 0.f), fmaxf(c[1][j], 0.f),
                                fmaxf(c[2][j], 0.f), fmaxf(c[3][j], 0.f));
        float4 v1 = make_float4(fmaxf(c[4][j], 0.f), fmaxf(c[5][j], 0.f),
                                fmaxf(c[6][j], 0.f), fmaxf(c[7][j], 0.f));
        *reinterpret_cast<float4*>(sRT + n * LDT + ty * 8)     = v0;
        *reinterpret_cast<float4*>(sRT + n * LDT + ty * 8 + 4) = v1;
    }
    __syncthreads();

    // GEMM2 + routing: one thread per token (threads 0..rows-1)
    int i0 = 0, i1 = 0, p0 = 0, p1 = 0;
    float w0 = 0.f, w1 = 0.f;
    bool active = (tid < rows);
    if (active) {
        float lg[E_NUM];
        #pragma unroll
        for (int e = 0; e < E_NUM; e++) lg[e] = rb2[e];
        for (int k = 0; k < RH_DIM; k++) {
            float r = sRT[k * LDT + tid];
            #pragma unroll
            for (int e = 0; e < E_NUM; e++) lg[e] += r * sW2[k * E_NUM + e];
        }
        // softmax over 6
        float mx = lg[0];
        #pragma unroll
        for (int e = 1; e < E_NUM; e++) mx = fmaxf(mx, lg[e]);
        float p[E_NUM]; float s = 0.f;
        #pragma unroll
        for (int e = 0; e < E_NUM; e++) { p[e] = expf(lg[e] - mx); s += p[e]; }
        float inv = 1.f / s;
        #pragma unroll
        for (int e = 0; e < E_NUM; e++) p[e] *= inv;
        // top-2 (first occurrence on ties, matching lax.top_k)
        i0 = 0;
        #pragma unroll
        for (int e = 1; e < E_NUM; e++) if (p[e] > p[i0]) i0 = e;
        i1 = (i0 == 0) ? 1 : 0;
        #pragma unroll
        for (int e = 0; e < E_NUM; e++)
            if (e != i0 && p[e] > p[i1]) i1 = e;
        // renormalizing softmax over the two selected probabilities
        float e1 = expf(p[i1] - p[i0]);       // <= 1
        w0 = 1.f / (1.f + e1);
        w1 = e1 * w0;
        p0 = atomicAdd(&s_cnt[i0], 1);
        p1 = atomicAdd(&s_cnt[i1], 1);
    }
    __syncthreads();
    if (tid < E_NUM) s_base[tid] = atomicAdd(&g_counts[tid], s_cnt[tid]);
    __syncthreads();
    if (active) {
        int tokid = t0 + tid;
        int o0 = i0 * T + s_base[i0] + p0;
        int o1 = i1 * T + s_base[i1] + p1;
        g_tok[o0] = tokid; g_wt[o0] = w0;
        g_tok[o1] = tokid; g_wt[o1] = w1;
    }
}

// ---------------------------------------------------------------------------
// 64x256x256 SGEMM piece: C(regs) = sSrc^T-tile @ W + b, weight staged 32 rows
// at a time through sW. sSrc layout: [K=256][LDT] (transposed activations).
// Thread tile: rows m = ty*8+i, cols n = tx+32*j (conflict-free b-frag).
// ---------------------------------------------------------------------------
__device__ __forceinline__ void mm64x256(const float* __restrict__ sSrc,
                                         float* __restrict__ sW,
                                         const float* __restrict__ w,
                                         const float* __restrict__ b,
                                         int tid, int tx, int ty,
                                         float c[8][8])
{
    #pragma unroll
    for (int j = 0; j < 8; j++) {
        float bv = b[tx + 32 * j];
        #pragma unroll
        for (int i = 0; i < 8; i++) c[i][j] = bv;
    }
    for (int k0 = 0; k0 < 256; k0 += 32) {
        __syncthreads();
        #pragma unroll
        for (int i = 0; i < 8; i++) {
            int idx = tid + i * 256;                 // 2048 float4 total
            int kk = idx >> 6, c4 = idx & 63;
            reinterpret_cast<float4*>(sW + kk * 256)[c4] =
                reinterpret_cast<const float4*>(w + (size_t)(k0 + kk) * 256)[c4];
        }
        __syncthreads();
        #pragma unroll 4
        for (int kk = 0; kk < 32; kk++) {
            const float* arow = sSrc + (k0 + kk) * LDT + ty * 8;
            float4 a0 = *reinterpret_cast<const float4*>(arow);
            float4 a1 = *reinterpret_cast<const float4*>(arow + 4);
            float a[8] = {a0.x, a0.y, a0.z, a0.w, a1.x, a1.y, a1.z, a1.w};
            float bb[8];
            #pragma unroll
            for (int j = 0; j < 8; j++) bb[j] = sW[kk * 256 + tx + 32 * j];
            #pragma unroll
            for (int i = 0; i < 8; i++)
                #pragma unroll
                for (int j = 0; j < 8; j++) c[i][j] += a[i] * bb[j];
        }
    }
}

__device__ __forceinline__ void store_act_relu(float* __restrict__ sDst,
                                               float c[8][8], int tx, int ty)
{
    #pragma unroll
    for (int j = 0; j < 8; j++) {
        int n = tx + 32 * j;
        float4 v0 = make_float4(fmaxf(c[0][j], 0.f), fmaxf(c[1][j], 0.f),
                                fmaxf(c[2][j], 0.f), fmaxf(c[3][j], 0.f));
        float4 v1 = make_float4(fmaxf(c[4][j], 0.f), fmaxf(c[5][j], 0.f),
                                fmaxf(c[6][j], 0.f), fmaxf(c[7][j], 0.f));
        *reinterpret_cast<float4*>(sDst + n * LDT + ty * 8)     = v0;
        *reinterpret_cast<float4*>(sDst + n * LDT + ty * 8 + 4) = v1;
    }
}

// ---------------------------------------------------------------------------
// Expert kernel: one block per (64-token tile of expert e's list).
// h1 = relu(X@W1+b1); h2 = relu(h1@W2+b2); out += wt * (h2@W3+b3)
// Exactly two atomicAdds per output element (onto 0) -> bitwise deterministic.
// ---------------------------------------------------------------------------
__global__ void __launch_bounds__(256)
expert_kernel(const float* __restrict__ feat,
              const float* __restrict__ ew1, const float* __restrict__ eb1,
              const float* __restrict__ ew2, const float* __restrict__ eb2,
              const float* __restrict__ ew3, const float* __restrict__ eb3,
              float* __restrict__ out, int T)
{
    int e = blockIdx.y;
    int cnt = g_counts[e];
    int m0 = blockIdx.x * TM;
    if (m0 >= cnt) return;
    int rows = min(TM, cnt - m0);

    extern __shared__ float sm[];
    float* sA = sm;                  // [256][LDT]
    float* sB = sA + 256 * LDT;      // [256][LDT]
    float* sW = sB + 256 * LDT;      // [32][256]

    __shared__ int   s_tok[TM];
    __shared__ float s_wt [TM];

    int tid = threadIdx.x;
    int tx = tid & 31, ty = tid >> 5;

    if (tid < TM) {
        int idx = m0 + ((tid < rows) ? tid : 0);
        s_tok[tid] = g_tok[e * T + idx];
        s_wt [tid] = (tid < rows) ? g_wt[e * T + m0 + tid] : 0.f;
    }
    __syncthreads();

    // gather X^T
    for (int idx = tid; idx < TM * (D_DIM / 4); idx += 256) {
        int m  = idx >> 6;
        int c4 = idx & 63;
        float4 v = reinterpret_cast<const float4*>(feat + (size_t)s_tok[m] * D_DIM)[c4];
        int k = c4 * 4;
        sA[(k + 0) * LDT + m] = v.x;
        sA[(k + 1) * LDT + m] = v.y;
        sA[(k + 2) * LDT + m] = v.z;
        sA[(k + 3) * LDT + m] = v.w;
    }
    // (first __syncthreads inside mm64x256 covers gather completion)

    float c[8][8];
    const size_t WSZ = (size_t)256 * 256;

    // GEMM1: h1 = relu(X @ W1 + b1)   sA -> sB
    mm64x256(sA, sW, ew1 + (size_t)e * WSZ, eb1 + e * H_DIM, tid, tx, ty, c);
    store_act_relu(sB, c, tx, ty);

    // GEMM2: h2 = relu(h1 @ W2 + b2)  sB -> sA
    mm64x256(sB, sW, ew2 + (size_t)e * WSZ, eb2 + e * H_DIM, tid, tx, ty, c);
    store_act_relu(sA, c, tx, ty);

    // GEMM3: y = h2 @ W3 + b3; out += wt * y
    mm64x256(sA, sW, ew3 + (size_t)e * WSZ, eb3 + e * D_DIM, tid, tx, ty, c);

    #pragma unroll
    for (int i = 0; i < 8; i++) {
        int m = ty * 8 + i;
        if (m < rows) {
            float wt = s_wt[m];
            float* op = out + (size_t)s_tok[m] * D_DIM;
            #pragma unroll
            for (int j = 0; j < 8; j++)
                atomicAdd(op + tx + 32 * j, wt * c[i][j]);
        }
    }
}

// ---------------------------------------------------------------------------
// Launch
// ---------------------------------------------------------------------------
extern "C" void kernel_launch(void* const* d_in, const int* in_sizes, int n_in,
                              void* d_out, int out_size)
{
    const float* feat = (const float*)d_in[0];
    const float* rw1  = (const float*)d_in[1];
    const float* rb1  = (const float*)d_in[2];
    const float* rw2  = (const float*)d_in[3];
    const float* rb2  = (const float*)d_in[4];
    const float* ew1  = (const float*)d_in[5];
    const float* eb1  = (const float*)d_in[6];
    const float* ew2  = (const float*)d_in[7];
    const float* eb2  = (const float*)d_in[8];
    const float* ew3  = (const float*)d_in[9];
    const float* eb3  = (const float*)d_in[10];
    float* out = (float*)d_out;

    int T = in_sizes[0] / D_DIM;

    const int RSMEM = (D_DIM * LDT + RH_DIM * LDT + 32 * RH_DIM + RH_DIM * E_NUM)
                      * (int)sizeof(float);                      // ~124 KB
    const int ESMEM = (2 * 256 * LDT + 32 * 256) * (int)sizeof(float); // 172 KB

    cudaFuncSetAttribute(router_kernel,
                         cudaFuncAttributeMaxDynamicSharedMemorySize, RSMEM);
    cudaFuncSetAttribute(expert_kernel,
                         cudaFuncAttributeMaxDynamicSharedMemorySize, ESMEM);

    zero_kernel<<<256, 256>>>((float4*)out, out_size / 4);

    int ntiles = (T + TM - 1) / TM;
    router_kernel<<<ntiles, 256, RSMEM>>>(feat, rw1, rb1, rw2, rb2, T);

    dim3 grid(ntiles, E_NUM);
    expert_kernel<<<grid, 256, ESMEM>>>(feat, ew1, eb1, ew2, eb2,
                                        ew3, eb3, out, T);
}

// round 11
// speedup vs baseline: 2.0639x; 2.0639x over previous
#include <cuda_runtime.h>
#include <cuda_bf16.h>
#include <math.h>
#include <stdint.h>

// ---------------------------------------------------------------------------
// MoE computed sparsely; expert GEMMs via mma.sync m16n8k16 bf16 with
// 3-term hi/lo split (AhBh + AlBh + AhBl) for ~fp32 accuracy.
// (tcgen05 is unavailable: harness PTX target is compute_103, not 103a.)
// B=8,S=4096 -> T=32768. D=H=256, E=6, TOP_K=2, ROUTER_H=128.
// ---------------------------------------------------------------------------

#define E_NUM   6
#define D_DIM   256
#define RH_DIM  128
#define MAX_T   32768
#define TM_R    64
#define LDT     68

// ---------------- device scratch -------------------------------------------
__device__ int   g_counts[E_NUM];
__device__ int   g_tok[E_NUM * MAX_T];
__device__ float g_wt [E_NUM * MAX_T];
// weights bf16, transposed [g][e][ver(hi/lo)][n=256][k=256] row-major
__device__ __align__(16) unsigned char g_wp[3 * 6 * 2 * 256 * 256 * 2];
// split features, row-major bf16 [T][256]
__device__ __align__(16) unsigned char g_xhi[MAX_T * 512];
__device__ __align__(16) unsigned char g_xlo[MAX_T * 512];

// ---------------- helpers ---------------------------------------------------
static __device__ __forceinline__ uint32_t smem_u32(const void* p) {
    uint32_t a;
    asm("{ .reg .u64 t; cvta.to.shared.u64 t, %1; cvt.u32.u64 %0, t; }"
        : "=r"(a) : "l"(p));
    return a;
}
static __device__ __forceinline__ void cp16(uint32_t dst, const void* src) {
    asm volatile("cp.async.cg.shared.global [%0], [%1], 16;\n"
                 :: "r"(dst), "l"(src));
}
#define CP_COMMIT() asm volatile("cp.async.commit_group;\n" ::: "memory")

static __device__ __forceinline__ void ldsm4(uint32_t r[4], uint32_t addr) {
    asm volatile("ldmatrix.sync.aligned.m8n8.x4.shared.b16 {%0,%1,%2,%3}, [%4];"
        : "=r"(r[0]), "=r"(r[1]), "=r"(r[2]), "=r"(r[3]) : "r"(addr));
}
static __device__ __forceinline__ void mma16816(float c[4], const uint32_t a[4],
                                                const uint32_t b[2]) {
    asm volatile("mma.sync.aligned.m16n8k16.row.col.f32.bf16.bf16.f32 "
        "{%0,%1,%2,%3}, {%4,%5,%6,%7}, {%8,%9}, {%0,%1,%2,%3};"
        : "+f"(c[0]), "+f"(c[1]), "+f"(c[2]), "+f"(c[3])
        : "r"(a[0]), "r"(a[1]), "r"(a[2]), "r"(a[3]), "r"(b[0]), "r"(b[1]));
}
static __device__ __forceinline__ void bsplit(float x, unsigned short& h,
                                              unsigned short& l) {
    __nv_bfloat16 hb = __float2bfloat16_rn(x);
    float r = x - __bfloat162float(hb);
    __nv_bfloat16 lb = __float2bfloat16_rn(r);
    h = __bfloat16_as_ushort(hb);
    l = __bfloat16_as_ushort(lb);
}

// ---------------------------------------------------------------------------
__global__ void zero_kernel(float4* __restrict__ out4, int n4)
{
    if (blockIdx.x == 0 && threadIdx.x < E_NUM) g_counts[threadIdx.x] = 0;
    int i = blockIdx.x * blockDim.x + threadIdx.x;
    int stride = gridDim.x * blockDim.x;
    float4 z = make_float4(0.f, 0.f, 0.f, 0.f);
    for (int k = i; k < n4; k += stride) out4[k] = z;
}

// fp32 [e][k][n] -> bf16 hi/lo, transposed rows [n][k].
__global__ void prep_weights(const float* __restrict__ ew1,
                             const float* __restrict__ ew2,
                             const float* __restrict__ ew3)
{
    int idx = blockIdx.x * blockDim.x + threadIdx.x;      // 3*6*256*32
    if (idx >= 3 * 6 * 256 * 32) return;
    int kc = idx & 31;            // 8-wide k chunk
    int n  = (idx >> 5) & 255;
    int ge = idx >> 13;
    int e  = ge % 6, g = ge / 6;
    const float* W = (g == 0 ? ew1 : (g == 1 ? ew2 : ew3)) + (size_t)e * 65536;
    int k0 = kc * 8;
    __align__(16) unsigned short hi[8], lo[8];
    #pragma unroll
    for (int i = 0; i < 8; i++)
        bsplit(W[(size_t)(k0 + i) * 256 + n], hi[i], lo[i]);
    size_t base = (size_t)((g * 6 + e) * 2) * 131072 + (size_t)n * 512 + k0 * 2;
    *reinterpret_cast<uint4*>(g_wp + base)          = *reinterpret_cast<uint4*>(hi);
    *reinterpret_cast<uint4*>(g_wp + base + 131072) = *reinterpret_cast<uint4*>(lo);
}

// fp32 [T][256] -> bf16 hi/lo rows.
__global__ void prep_feat(const float* __restrict__ feat, int T)
{
    int idx = blockIdx.x * blockDim.x + threadIdx.x;      // T*32
    int t = idx >> 5, c = idx & 31;
    if (t >= T) return;
    const float4* src = reinterpret_cast<const float4*>(feat + (size_t)t * 256) + c * 2;
    float4 v0 = src[0], v1 = src[1];
    float f[8] = {v0.x, v0.y, v0.z, v0.w, v1.x, v1.y, v1.z, v1.w};
    __align__(16) unsigned short hi[8], lo[8];
    #pragma unroll
    for (int i = 0; i < 8; i++) bsplit(f[i], hi[i], lo[i]);
    size_t off = (size_t)t * 512 + c * 16;
    *reinterpret_cast<uint4*>(g_xhi + off) = *reinterpret_cast<uint4*>(hi);
    *reinterpret_cast<uint4*>(g_xlo + off) = *reinterpret_cast<uint4*>(lo);
}

// ---------------------------------------------------------------------------
// Router (byte-identical logic to the proven 801us/4.8e-8 version).
// ---------------------------------------------------------------------------
__global__ void __launch_bounds__(256)
router_kernel(const float* __restrict__ feat,
              const float* __restrict__ rw1, const float* __restrict__ rb1,
              const float* __restrict__ rw2, const float* __restrict__ rb2,
              int T)
{
    extern __shared__ float sm[];
    float* sXT = sm;
    float* sRT = sXT + D_DIM * LDT;
    float* sW  = sRT + RH_DIM * LDT;
    float* sW2 = sW + 32 * RH_DIM;

    __shared__ int s_cnt[E_NUM];
    __shared__ int s_base[E_NUM];

    int tid = threadIdx.x;
    int tx = tid & 31, ty = tid >> 5;
    int t0 = blockIdx.x * TM_R;
    int rows = min(TM_R, T - t0);

    if (tid < E_NUM) s_cnt[tid] = 0;
    for (int i = tid; i < RH_DIM * E_NUM; i += 256) sW2[i] = rw2[i];

    for (int idx = tid; idx < TM_R * (D_DIM / 4); idx += 256) {
        int m  = idx >> 6;
        int c4 = idx & 63;
        int trow = t0 + ((m < rows) ? m : 0);
        float4 v = reinterpret_cast<const float4*>(feat + (size_t)trow * D_DIM)[c4];
        int k = c4 * 4;
        sXT[(k + 0) * LDT + m] = v.x;
        sXT[(k + 1) * LDT + m] = v.y;
        sXT[(k + 2) * LDT + m] = v.z;
        sXT[(k + 3) * LDT + m] = v.w;
    }

    float c[8][4];
    #pragma unroll
    for (int j = 0; j < 4; j++) {
        float bv = rb1[tx + 32 * j];
        #pragma unroll
        for (int i = 0; i < 8; i++) c[i][j] = bv;
    }
    for (int k0 = 0; k0 < D_DIM; k0 += 32) {
        __syncthreads();
        #pragma unroll
        for (int i = 0; i < 4; i++) {
            int idx = tid + i * 256;
            int kk = idx >> 5, c4 = idx & 31;
            reinterpret_cast<float4*>(sW + kk * RH_DIM)[c4] =
                reinterpret_cast<const float4*>(rw1 + (size_t)(k0 + kk) * RH_DIM)[c4];
        }
        __syncthreads();
        #pragma unroll 4
        for (int kk = 0; kk < 32; kk++) {
            const float* arow = sXT + (k0 + kk) * LDT + ty * 8;
            float4 a0 = *reinterpret_cast<const float4*>(arow);
            float4 a1 = *reinterpret_cast<const float4*>(arow + 4);
            float a[8] = {a0.x, a0.y, a0.z, a0.w, a1.x, a1.y, a1.z, a1.w};
            float bb[4];
            #pragma unroll
            for (int j = 0; j < 4; j++) bb[j] = sW[kk * RH_DIM + tx + 32 * j];
            #pragma unroll
            for (int i = 0; i < 8; i++)
                #pragma unroll
                for (int j = 0; j < 4; j++) c[i][j] += a[i] * bb[j];
        }
    }
    #pragma unroll
    for (int j = 0; j < 4; j++) {
        int n = tx + 32 * j;
        float4 v0 = make_float4(fmaxf(c[0][j], 0.f), fmaxf(c[1][j], 0.f),
                                fmaxf(c[2][j], 0.f), fmaxf(c[3][j], 0.f));
        float4 v1 = make_float4(fmaxf(c[4][j], 0.f), fmaxf(c[5][j], 0.f),
                                fmaxf(c[6][j], 0.f), fmaxf(c[7][j], 0.f));
        *reinterpret_cast<float4*>(sRT + n * LDT + ty * 8)     = v0;
        *reinterpret_cast<float4*>(sRT + n * LDT + ty * 8 + 4) = v1;
    }
    __syncthreads();

    int i0 = 0, i1 = 0, p0 = 0, p1 = 0;
    float w0 = 0.f, w1 = 0.f;
    bool active = (tid < rows);
    if (active) {
        float lg[E_NUM];
        #pragma unroll
        for (int e = 0; e < E_NUM; e++) lg[e] = rb2[e];
        for (int k = 0; k < RH_DIM; k++) {
            float r = sRT[k * LDT + tid];
            #pragma unroll
            for (int e = 0; e < E_NUM; e++) lg[e] += r * sW2[k * E_NUM + e];
        }
        float mx = lg[0];
        #pragma unroll
        for (int e = 1; e < E_NUM; e++) mx = fmaxf(mx, lg[e]);
        float p[E_NUM]; float s = 0.f;
        #pragma unroll
        for (int e = 0; e < E_NUM; e++) { p[e] = expf(lg[e] - mx); s += p[e]; }
        float inv = 1.f / s;
        #pragma unroll
        for (int e = 0; e < E_NUM; e++) p[e] *= inv;
        i0 = 0;
        #pragma unroll
        for (int e = 1; e < E_NUM; e++) if (p[e] > p[i0]) i0 = e;
        i1 = (i0 == 0) ? 1 : 0;
        #pragma unroll
        for (int e = 0; e < E_NUM; e++)
            if (e != i0 && p[e] > p[i1]) i1 = e;
        float e1 = expf(p[i1] - p[i0]);
        w0 = 1.f / (1.f + e1);
        w1 = e1 * w0;
        p0 = atomicAdd(&s_cnt[i0], 1);
        p1 = atomicAdd(&s_cnt[i1], 1);
    }
    __syncthreads();
    if (tid < E_NUM) s_base[tid] = atomicAdd(&g_counts[tid], s_cnt[tid]);
    __syncthreads();
    if (active) {
        int tokid = t0 + tid;
        int o0 = i0 * T + s_base[i0] + p0;
        int o1 = i1 * T + s_base[i1] + p1;
        g_tok[o0] = tokid; g_wt[o0] = w0;
        g_tok[o1] = tokid; g_wt[o1] = w1;
    }
}

// ---------------------------------------------------------------------------
// Expert kernel. 512 threads = 16 warps (2m x 8n), tile M128 x N256, K=256.
// SMEM:
//   A full (hi,lo): [128 rows][264 halves] each  (stride 528B; 16B pad)
//   B stage: 2 buf x (hi,lo) x [256 n][40 halves] (stride 80B), 32-k stages
//   bias 3x256 f32, tok 128, wt 128
// ---------------------------------------------------------------------------
#define A_STRIDE  528
#define A_VER     67584          /* 128*528 */
#define B_ROW     80
#define B_VER     20480          /* 256*80 */
#define B_BUF     40960
#define SM_AF     0
#define SM_B      135168
#define SM_BIAS   217088
#define SM_TOK    220160
#define SM_WT     220672
#define ESMEM     221184

static __device__ __forceinline__
void loadB(uint32_t sB, const unsigned char* wbase, int s, int buf, int tid) {
    #pragma unroll
    for (int i = 0; i < 4; i++) {
        int q = tid + i * 512;                 // 2048 x 16B
        int ver = q >> 10;
        int rem = q & 1023;
        int n = rem >> 2, cc = rem & 3;
        cp16(sB + buf * B_BUF + ver * B_VER + n * B_ROW + cc * 16,
             wbase + (size_t)ver * 131072 + (size_t)n * 512 + s * 64 + cc * 16);
    }
}

__global__ void __launch_bounds__(512, 1)
expert_kernel(const float* __restrict__ eb1, const float* __restrict__ eb2,
              const float* __restrict__ eb3, float* __restrict__ out, int T)
{
    int e = blockIdx.y;
    int cnt = g_counts[e];
    int m0 = blockIdx.x * 128;
    if (m0 >= cnt) return;
    int rows = min(128, cnt - m0);

    extern __shared__ char smc[];
    float* s_bias = (float*)(smc + SM_BIAS);
    int*   s_tok  = (int*)(smc + SM_TOK);
    float* s_wt   = (float*)(smc + SM_WT);

    uint32_t sbase = smem_u32(smc);
    uint32_t sA = sbase + SM_AF;
    uint32_t sB = sbase + SM_B;

    int tid  = threadIdx.x;
    int lane = tid & 31, wid = tid >> 5;
    int wm = wid & 1, wn = wid >> 1;

    if (tid < 128) {
        int i = m0 + min(tid, rows - 1);
        s_tok[tid] = g_tok[e * T + i];
        s_wt [tid] = (tid < rows) ? g_wt[e * T + m0 + tid] : 0.f;
    }
    {
        int i = tid;            // 512 threads, 768 bias values
        s_bias[i] = (i < 256) ? eb1[(size_t)e * 256 + i]
                              : eb2[(size_t)e * 256 + (i - 256)];
        if (i < 256) s_bias[512 + i] = eb3[(size_t)e * 256 + i];
    }
    __syncthreads();

    // per-thread ldmatrix base addresses
    uint32_t a_base = sA + (uint32_t)((wm * 64 + (lane & 15)) * A_STRIDE)
                         + (uint32_t)(((lane >> 4) & 1) * 16);
    uint32_t b_base0 = sB + (uint32_t)((wn * 32 + (lane & 7) + ((lane >> 4) & 1) * 8) * B_ROW)
                          + (uint32_t)(((lane >> 3) & 1) * 16);

    float c[4][4][4];

    #pragma unroll 1
    for (int g = 0; g < 3; g++) {
        const unsigned char* wbase = g_wp + (size_t)((g * 6 + e) * 2) * 131072;

        // issue first two B stages (+ A gather on g==0)
        if (g == 0) {
            #pragma unroll
            for (int i = 0; i < 16; i++) {
                int q = tid + i * 512;              // 8192 x 16B
                int ver = q >> 12;
                int rem = q & 4095;
                int r = rem >> 5, cc = rem & 31;
                const unsigned char* src = (ver ? g_xlo : g_xhi)
                    + (size_t)s_tok[r] * 512 + cc * 16;
                cp16(sA + ver * A_VER + r * A_STRIDE + cc * 16, src);
            }
        }
        loadB(sB, wbase, 0, 0, tid); CP_COMMIT();
        loadB(sB, wbase, 1, 1, tid); CP_COMMIT();

        #pragma unroll
        for (int mt = 0; mt < 4; mt++)
            #pragma unroll
            for (int nt = 0; nt < 4; nt++)
                #pragma unroll
                for (int r = 0; r < 4; r++) c[mt][nt][r] = 0.f;

        #pragma unroll 1
        for (int s = 0; s < 8; s++) {
            if (s < 7) asm volatile("cp.async.wait_group 1;" ::: "memory");
            else       asm volatile("cp.async.wait_group 0;" ::: "memory");
            __syncthreads();
            int buf = s & 1;
            uint32_t bb = b_base0 + (uint32_t)(buf * B_BUF);

            #pragma unroll
            for (int k2 = 0; k2 < 2; k2++) {
                uint32_t kg = (uint32_t)((s * 32 + k2 * 16) * 2);   // bytes in A
                uint32_t kl = (uint32_t)((k2 * 16) * 2);            // bytes in B
                uint32_t ah[4][4], bh[2][4], bl[2][4];
                #pragma unroll
                for (int mt = 0; mt < 4; mt++)
                    ldsm4(ah[mt], a_base + mt * (16 * A_STRIDE) + kg);
                #pragma unroll
                for (int p = 0; p < 2; p++) {
                    ldsm4(bh[p], bb + p * (16 * B_ROW) + kl);
                    ldsm4(bl[p], bb + B_VER + p * (16 * B_ROW) + kl);
                }
                #pragma unroll
                for (int mt = 0; mt < 4; mt++)
                    #pragma unroll
                    for (int nt = 0; nt < 4; nt++) {
                        mma16816(c[mt][nt], ah[mt], &bh[nt >> 1][(nt & 1) * 2]);
                        mma16816(c[mt][nt], ah[mt], &bl[nt >> 1][(nt & 1) * 2]);
                    }
                uint32_t al[4][4];
                #pragma unroll
                for (int mt = 0; mt < 4; mt++)
                    ldsm4(al[mt], a_base + A_VER + mt * (16 * A_STRIDE) + kg);
                #pragma unroll
                for (int mt = 0; mt < 4; mt++)
                    #pragma unroll
                    for (int nt = 0; nt < 4; nt++)
                        mma16816(c[mt][nt], al[mt], &bh[nt >> 1][(nt & 1) * 2]);
            }
            __syncthreads();
            if (s < 6) { loadB(sB, wbase, s + 2, buf, tid); CP_COMMIT(); }
        }
        // (last __syncthreads above = post-GEMM barrier: all reads of A done)

        int q = lane >> 2, t = lane & 3;
        if (g < 2) {
            const float* bp = s_bias + g * 256;
            #pragma unroll
            for (int mt = 0; mt < 4; mt++)
                #pragma unroll
                for (int nt = 0; nt < 4; nt++) {
                    int col = wn * 32 + nt * 8 + t * 2;
                    float b0 = bp[col], b1 = bp[col + 1];
                    #pragma unroll
                    for (int h = 0; h < 2; h++) {
                        int row = wm * 64 + mt * 16 + q + h * 8;
                        float v0 = fmaxf(c[mt][nt][2 * h]     + b0, 0.f);
                        float v1 = fmaxf(c[mt][nt][2 * h + 1] + b1, 0.f);
                        unsigned short h0, l0, h1, l1;
                        bsplit(v0, h0, l0); bsplit(v1, h1, l1);
                        uint32_t hw = (uint32_t)h0 | ((uint32_t)h1 << 16);
                        uint32_t lw = (uint32_t)l0 | ((uint32_t)l1 << 16);
                        uint32_t off = (uint32_t)(row * A_STRIDE + col * 2);
                        asm volatile("st.shared.b32 [%0], %1;"
                                     :: "r"(sA + off), "r"(hw) : "memory");
                        asm volatile("st.shared.b32 [%0], %1;"
                                     :: "r"(sA + A_VER + off), "r"(lw) : "memory");
                    }
                }
        } else {
            const float* bp = s_bias + 512;
            #pragma unroll
            for (int mt = 0; mt < 4; mt++)
                #pragma unroll
                for (int h = 0; h < 2; h++) {
                    int row = wm * 64 + mt * 16 + q + h * 8;
                    if (row < rows) {
                        float wt = s_wt[row];
                        float* op = out + (size_t)s_tok[row] * 256;
                        #pragma unroll
                        for (int nt = 0; nt < 4; nt++) {
                            int col = wn * 32 + nt * 8 + t * 2;
                            atomicAdd(op + col,
                                      wt * (c[mt][nt][2 * h] + bp[col]));
                            atomicAdd(op + col + 1,
                                      wt * (c[mt][nt][2 * h + 1] + bp[col + 1]));
                        }
                    }
                }
        }
    }
}

// ---------------------------------------------------------------------------
extern "C" void kernel_launch(void* const* d_in, const int* in_sizes, int n_in,
                              void* d_out, int out_size)
{
    const float* feat = (const float*)d_in[0];
    const float* rw1  = (const float*)d_in[1];
    const float* rb1  = (const float*)d_in[2];
    const float* rw2  = (const float*)d_in[3];
    const float* rb2  = (const float*)d_in[4];
    const float* ew1  = (const float*)d_in[5];
    const float* eb1  = (const float*)d_in[6];
    const float* ew2  = (const float*)d_in[7];
    const float* eb2  = (const float*)d_in[8];
    const float* ew3  = (const float*)d_in[9];
    const float* eb3  = (const float*)d_in[10];
    float* out = (float*)d_out;

    int T = in_sizes[0] / D_DIM;

    const int RSMEM = (D_DIM * LDT + RH_DIM * LDT + 32 * RH_DIM + RH_DIM * E_NUM)
                      * (int)sizeof(float);
    cudaFuncSetAttribute(router_kernel,
                         cudaFuncAttributeMaxDynamicSharedMemorySize, RSMEM);
    cudaFuncSetAttribute(expert_kernel,
                         cudaFuncAttributeMaxDynamicSharedMemorySize, ESMEM);

    zero_kernel<<<256, 256>>>((float4*)out, out_size / 4);
    prep_feat<<<(T * 32 + 255) / 256, 256>>>(feat, T);
    prep_weights<<<576, 256>>>(ew1, ew2, ew3);

    int rtiles = (T + TM_R - 1) / TM_R;
    router_kernel<<<rtiles, 256, RSMEM>>>(feat, rw1, rb1, rw2, rb2, T);

    int etiles = (T + 127) / 128;
    dim3 grid(etiles, E_NUM);
    expert_kernel<<<grid, 512, ESMEM>>>(eb1, eb2, eb3, out, T);
}